// round 5
// baseline (speedup 1.0000x reference)
#include <cuda_runtime.h>

#define N_NODES 100000
#define N_EDGES 1600000
#define DIM 128
#define HID 16
#define NCLS 40
#define BN_EPS 1e-5f

typedef unsigned long long ull;

// ---------------- f32x2 packed-math helpers (B300 FFMA2 path) --------------
__device__ __forceinline__ ull pack2(float x, float y) {
    ull r; asm("mov.b64 %0,{%1,%2};" : "=l"(r) : "f"(x), "f"(y)); return r;
}
__device__ __forceinline__ void unpack2(ull v, float& x, float& y) {
    asm("mov.b64 {%0,%1},%2;" : "=f"(x), "=f"(y) : "l"(v));
}
__device__ __forceinline__ ull fma2(ull a, ull b, ull c) {
    ull d; asm("fma.rn.f32x2 %0,%1,%2,%3;" : "=l"(d) : "l"(a), "l"(b), "l"(c)); return d;
}

// ---------------- scratch (static device globals) ---------------------------
__device__ float  g_h1[N_NODES * HID];
__device__ float  g_s1[N_NODES * HID];
__device__ float  g_agg[N_NODES * HID];
__device__ double g_sum16[HID];
__device__ double g_M[HID * HID];
__device__ float  g_scale[DIM];
__device__ float  g_shift[DIM];
__device__ int    g_row_ptr[N_NODES + 1];
__device__ unsigned int g_cnt = 0;

#define TB 256
#define NODE_BLK ((N_NODES + TB - 1) / TB)          // 391
#define RP_BLK   ((N_NODES + 1 + TB - 1) / TB)      // 391
#define SPMM_BLK ((N_NODES + 15) / 16)              // 6250 (16 threads/row)
#define STATS_G  512
#define STATS_TILE 64
#define N_TILES  ((N_NODES + STATS_TILE - 1) / STATS_TILE)   // 1563

// ---------------- fused: row_ptr build + y[N,16] = x[N,128] @ W[128,16] ----
__global__ void prolog_kernel(const int* __restrict__ row, const float* __restrict__ x,
                              const float* __restrict__ W, float* __restrict__ y) {
    if (blockIdx.x >= NODE_BLK) {
        int i = (blockIdx.x - NODE_BLK) * TB + threadIdx.x;
        if (i > N_NODES) return;
        int lo = 0, hi = N_EDGES;
        while (lo < hi) {
            int mid = (lo + hi) >> 1;
            if (row[mid] < i) lo = mid + 1; else hi = mid;
        }
        g_row_ptr[i] = lo;
        return;
    }
    __shared__ __align__(16) float Ws[DIM * HID];
    for (int i = threadIdx.x; i < DIM * HID; i += TB) Ws[i] = W[i];
    __syncthreads();
    int n = blockIdx.x * TB + threadIdx.x;
    if (n >= N_NODES) return;
    ull acc2[8];
    #pragma unroll
    for (int j = 0; j < 8; j++) acc2[j] = 0ull;
    const float4* xr = reinterpret_cast<const float4*>(x + (size_t)n * DIM);
    #pragma unroll 4
    for (int d4 = 0; d4 < DIM / 4; d4++) {
        float4 xv = xr[d4];
        #pragma unroll
        for (int dd = 0; dd < 4; dd++) {
            float xd = (&xv.x)[dd];
            ull xb = pack2(xd, xd);
            const ulonglong2* wr = reinterpret_cast<const ulonglong2*>(&Ws[(d4 * 4 + dd) * HID]);
            #pragma unroll
            for (int p = 0; p < 4; p++) {
                ulonglong2 w = wr[p];
                acc2[p * 2 + 0] = fma2(xb, w.x, acc2[p * 2 + 0]);
                acc2[p * 2 + 1] = fma2(xb, w.y, acc2[p * 2 + 1]);
            }
        }
    }
    ull* yr = reinterpret_cast<ull*>(y + (size_t)n * HID);
    #pragma unroll
    for (int j = 0; j < 8; j++) yr[j] = acc2[j];
}

// ---------------- 16-wide SpMM: 16 threads/row (4 quads), float4 gathers ----
template<bool RELU, bool ZERO_STATS>
__global__ void spmm16(const float4* __restrict__ h, const float* __restrict__ vals,
                       const int* __restrict__ col, const float4* __restrict__ bias4,
                       float4* __restrict__ out) {
    if (ZERO_STATS && blockIdx.x == 0) {
        int t = threadIdx.x;
        if (t < HID * HID) g_M[t] = 0.0;
        if (t < HID) g_sum16[t] = 0.0;
    }
    int t = threadIdx.x;
    int q = t & 3;
    int sub = (t >> 2) & 3;
    int r = blockIdx.x * 16 + (t >> 4);
    if (r >= N_NODES) return;
    int e0 = g_row_ptr[r], e1 = g_row_ptr[r + 1];
    float4 acc = make_float4(0.f, 0.f, 0.f, 0.f);
    int e = e0 + sub * 4;
    while (e + 4 <= e1) {
        int   c0 = col[e],     c1 = col[e + 1],  c2 = col[e + 2],  c3 = col[e + 3];
        float v0 = vals[e],    v1 = vals[e + 1], v2 = vals[e + 2], v3 = vals[e + 3];
        float4 h0 = h[(size_t)c0 * 4 + q];
        float4 h1 = h[(size_t)c1 * 4 + q];
        float4 h2 = h[(size_t)c2 * 4 + q];
        float4 h3 = h[(size_t)c3 * 4 + q];
        acc.x += v0 * h0.x; acc.y += v0 * h0.y; acc.z += v0 * h0.z; acc.w += v0 * h0.w;
        acc.x += v1 * h1.x; acc.y += v1 * h1.y; acc.z += v1 * h1.z; acc.w += v1 * h1.w;
        acc.x += v2 * h2.x; acc.y += v2 * h2.y; acc.z += v2 * h2.z; acc.w += v2 * h2.w;
        acc.x += v3 * h3.x; acc.y += v3 * h3.y; acc.z += v3 * h3.z; acc.w += v3 * h3.w;
        e += 16;
    }
    int eend = min(e + 4, e1);
    for (; e < eend; e++) {
        float v = vals[e];
        float4 hv = h[(size_t)col[e] * 4 + q];
        acc.x += v * hv.x; acc.y += v * hv.y; acc.z += v * hv.z; acc.w += v * hv.w;
    }
    // combine 4 sub-quads of this row (lanes differing in bits 2,3)
    #pragma unroll
    for (int m = 4; m <= 8; m <<= 1) {
        acc.x += __shfl_xor_sync(0xffffffffu, acc.x, m);
        acc.y += __shfl_xor_sync(0xffffffffu, acc.y, m);
        acc.z += __shfl_xor_sync(0xffffffffu, acc.z, m);
        acc.w += __shfl_xor_sync(0xffffffffu, acc.w, m);
    }
    if (sub == 0) {
        if (RELU) {
            float4 b = bias4[q];
            acc.x = fmaxf(acc.x + b.x, 0.f);
            acc.y = fmaxf(acc.y + b.y, 0.f);
            acc.z = fmaxf(acc.z + b.z, 0.f);
            acc.w = fmaxf(acc.w + b.w, 0.f);
        }
        out[(size_t)r * 4 + q] = acc;
    }
}

// ---------------- stats: thread-per-M-entry, shared row tiles, no shuffles --
// thread t owns M[j][k], j=t>>4, k=t&15.  Last block computes BN affine.
__global__ void stats16_bn(const float* __restrict__ agg,
                           const float* __restrict__ W2,
                           const float* __restrict__ gamma,
                           const float* __restrict__ beta) {
    __shared__ __align__(16) float rows[STATS_TILE * HID];   // 4KB
    int t = threadIdx.x;
    int j = t >> 4, k = t & 15;
    float accM = 0.f, accS = 0.f;
    for (int tile = blockIdx.x; tile < N_TILES; tile += STATS_G) {
        int r0 = tile * STATS_TILE;
        int nr = min(STATS_TILE, N_NODES - r0);
        __syncthreads();
        if (t < nr * 4)
            reinterpret_cast<float4*>(rows)[t] =
                reinterpret_cast<const float4*>(agg + (size_t)r0 * HID)[t];
        __syncthreads();
        for (int rr = 0; rr < nr; rr++) {
            float aj = rows[rr * HID + j];
            float ak = rows[rr * HID + k];
            accM += aj * ak;
            if (j == 0) accS += ak;
        }
    }
    atomicAdd(&g_M[t], (double)accM);
    if (t < HID) atomicAdd(&g_sum16[t], (double)accS);

    // ---- last block computes BN affine ----
    __threadfence();
    __shared__ unsigned int sIsLast;
    if (t == 0) {
        unsigned int old = atomicAdd(&g_cnt, 1u);
        sIsLast = (old == gridDim.x - 1) ? 1u : 0u;
    }
    __syncthreads();
    if (!sIsLast) return;
    __shared__ double Ms[HID * HID];
    __shared__ double Ss[HID];
    Ms[t] = g_M[t];
    if (t < HID) Ss[t] = g_sum16[t];
    __syncthreads();
    if (t < DIM) {
        double w[HID];
        #pragma unroll
        for (int kk = 0; kk < HID; kk++) w[kk] = (double)W2[kk * DIM + t];
        double sm = 0.0;
        #pragma unroll
        for (int kk = 0; kk < HID; kk++) sm += Ss[kk] * w[kk];
        double qv = 0.0;
        #pragma unroll
        for (int a = 0; a < HID; a++) {
            double wa = w[a];
            #pragma unroll
            for (int b = 0; b < HID; b++) qv += Ms[a * HID + b] * wa * w[b];
        }
        const double invN = 1.0 / (double)N_NODES;
        double sn = sm * invN;
        float var = (float)(qv * invN - sn * sn);
        float scale = rsqrtf(var + BN_EPS) * gamma[t];
        g_scale[t] = scale;
        g_shift[t] = beta[t] - (float)sn * scale;   // b2 cancels in (h2-mean)
    }
    if (t == 0) g_cnt = 0;
}

// ---------------- fused: h1 = relu(bn(agg@W2)) @ W1next  (f32x2 packed) -----
__global__ void fused_bn_gemm(const float* __restrict__ agg, const float* __restrict__ W2,
                              const float* __restrict__ W1n, float* __restrict__ y) {
    __shared__ __align__(16) float W2s[HID * DIM];
    __shared__ __align__(16) float W1s[DIM * HID];
    __shared__ __align__(16) float scl[DIM];
    __shared__ __align__(16) float sft[DIM];
    for (int i = threadIdx.x; i < HID * DIM; i += TB) {
        W2s[i] = W2[i];
        W1s[i] = W1n[i];
    }
    for (int i = threadIdx.x; i < DIM; i += TB) {
        scl[i] = g_scale[i];
        sft[i] = g_shift[i];
    }
    __syncthreads();
    int n = blockIdx.x * TB + threadIdx.x;
    if (n >= N_NODES) return;
    ull a2[HID];
    {
        const float4* ar = reinterpret_cast<const float4*>(agg + (size_t)n * HID);
        #pragma unroll
        for (int k4 = 0; k4 < 4; k4++) {
            float4 v = ar[k4];
            a2[k4*4+0] = pack2(v.x, v.x);
            a2[k4*4+1] = pack2(v.y, v.y);
            a2[k4*4+2] = pack2(v.z, v.z);
            a2[k4*4+3] = pack2(v.w, v.w);
        }
    }
    ull acc2[8];
    #pragma unroll
    for (int j = 0; j < 8; j++) acc2[j] = 0ull;
    #pragma unroll 2
    for (int cb = 0; cb < DIM; cb += 4) {
        ull t01 = 0ull, t23 = 0ull;
        const ulonglong2* w2p = reinterpret_cast<const ulonglong2*>(&W2s[cb]);
        #pragma unroll
        for (int k = 0; k < HID; k++) {
            ulonglong2 w = w2p[k * (DIM / 4)];
            t01 = fma2(a2[k], w.x, t01);
            t23 = fma2(a2[k], w.y, t23);
        }
        ulonglong2 sc = *reinterpret_cast<const ulonglong2*>(&scl[cb]);
        ulonglong2 sf = *reinterpret_cast<const ulonglong2*>(&sft[cb]);
        t01 = fma2(t01, sc.x, sf.x);
        t23 = fma2(t23, sc.y, sf.y);
        float v0, v1, v2, v3;
        unpack2(t01, v0, v1);
        unpack2(t23, v2, v3);
        v0 = fmaxf(v0, 0.f); v1 = fmaxf(v1, 0.f);
        v2 = fmaxf(v2, 0.f); v3 = fmaxf(v3, 0.f);
        ull vb[4] = { pack2(v0, v0), pack2(v1, v1), pack2(v2, v2), pack2(v3, v3) };
        #pragma unroll
        for (int c = 0; c < 4; c++) {
            const ulonglong2* w1p = reinterpret_cast<const ulonglong2*>(&W1s[(cb + c) * HID]);
            #pragma unroll
            for (int p = 0; p < 4; p++) {
                ulonglong2 w = w1p[p];
                acc2[p * 2 + 0] = fma2(vb[c], w.x, acc2[p * 2 + 0]);
                acc2[p * 2 + 1] = fma2(vb[c], w.y, acc2[p * 2 + 1]);
            }
        }
    }
    ull* yr = reinterpret_cast<ull*>(y + (size_t)n * HID);
    #pragma unroll
    for (int j = 0; j < 8; j++) yr[j] = acc2[j];
}

// ---------------- out[N,40] = agg[N,16] @ W[16,40] + b  (f32x2 packed) ------
__global__ void out_gemm(const float* __restrict__ agg, const float* __restrict__ W,
                         const float* __restrict__ b, float* __restrict__ out) {
    __shared__ __align__(16) float Ws[HID * NCLS];
    __shared__ __align__(16) float bs[NCLS];
    for (int i = threadIdx.x; i < HID * NCLS; i += TB) Ws[i] = W[i];
    if (threadIdx.x < NCLS) bs[threadIdx.x] = b[threadIdx.x];
    __syncthreads();
    int n = blockIdx.x * TB + threadIdx.x;
    if (n >= N_NODES) return;
    ull a2[HID];
    {
        const float4* ar = reinterpret_cast<const float4*>(agg + (size_t)n * HID);
        #pragma unroll
        for (int k4 = 0; k4 < 4; k4++) {
            float4 v = ar[k4];
            a2[k4*4+0] = pack2(v.x, v.x);
            a2[k4*4+1] = pack2(v.y, v.y);
            a2[k4*4+2] = pack2(v.z, v.z);
            a2[k4*4+3] = pack2(v.w, v.w);
        }
    }
    ull o2[NCLS / 2];
    const ull* bp = reinterpret_cast<const ull*>(bs);
    #pragma unroll
    for (int p = 0; p < NCLS / 2; p++) o2[p] = bp[p];
    #pragma unroll
    for (int k = 0; k < HID; k++) {
        const ull* wr = reinterpret_cast<const ull*>(&Ws[k * NCLS]);
        #pragma unroll
        for (int p = 0; p < NCLS / 2; p++)
            o2[p] = fma2(a2[k], wr[p], o2[p]);
    }
    ull* orow = reinterpret_cast<ull*>(out + (size_t)n * NCLS);
    #pragma unroll
    for (int p = 0; p < NCLS / 2; p++) orow[p] = o2[p];
}

// ============================================================================
extern "C" void kernel_launch(void* const* d_in, const int* in_sizes, int n_in,
                              void* d_out, int out_size) {
    const float* x     = (const float*)d_in[0];
    const float* vals  = (const float*)d_in[1];
    const float* W1    = (const float*)d_in[2];   // (3,128,16)
    const float* b1    = (const float*)d_in[3];   // (3,16)
    const float* W2    = (const float*)d_in[4];   // (3,16,128)
    const float* b2    = (const float*)d_in[5];   // (3,128)  (cancels in BN)
    const float* gamma = (const float*)d_in[6];   // (3,128)
    const float* beta  = (const float*)d_in[7];   // (3,128)
    const float* W1f   = (const float*)d_in[8];   // (128,16)
    const float* b1f   = (const float*)d_in[9];   // (16,)
    const float* W2f   = (const float*)d_in[10];  // (16,40)
    const float* b2f   = (const float*)d_in[11];  // (40,)
    const int*   row   = (const int*)d_in[12];
    const int*   col   = (const int*)d_in[13];
    float* out = (float*)d_out;
    (void)b2;

    float *p_h1, *p_s1, *p_agg;
    cudaGetSymbolAddress((void**)&p_h1,  g_h1);
    cudaGetSymbolAddress((void**)&p_s1,  g_s1);
    cudaGetSymbolAddress((void**)&p_agg, g_agg);

    prolog_kernel<<<NODE_BLK + RP_BLK, TB>>>(row, x, W1, p_h1);

    for (int i = 0; i < 3; i++) {
        spmm16<true, true><<<SPMM_BLK, TB>>>((const float4*)p_h1, vals, col,
                                             (const float4*)(b1 + i * HID), (float4*)p_s1);
        spmm16<false, false><<<SPMM_BLK, TB>>>((const float4*)p_s1, vals, col,
                                               nullptr, (float4*)p_agg);
        stats16_bn<<<STATS_G, TB>>>(p_agg, W2 + (size_t)i * HID * DIM,
                                    gamma + i * DIM, beta + i * DIM);
        const float* Wnext = (i < 2) ? (W1 + (size_t)(i + 1) * DIM * HID) : W1f;
        fused_bn_gemm<<<NODE_BLK, TB>>>(p_agg, W2 + (size_t)i * HID * DIM, Wnext, p_h1);
    }

    spmm16<true, false><<<SPMM_BLK, TB>>>((const float4*)p_h1, vals, col,
                                          (const float4*)b1f, (float4*)p_s1);
    spmm16<false, false><<<SPMM_BLK, TB>>>((const float4*)p_s1, vals, col,
                                           nullptr, (float4*)p_agg);
    out_gemm<<<NODE_BLK, TB>>>(p_agg, W2f, b2f, out);
}

// round 6
// speedup vs baseline: 1.0155x; 1.0155x over previous
#include <cuda_runtime.h>

#define N_NODES 100000
#define N_EDGES 1600000
#define DIM 128
#define HID 16
#define NCLS 40
#define BN_EPS 1e-5f

typedef unsigned long long ull;

// ---------------- f32x2 packed-math helpers (B300 FFMA2 path) --------------
__device__ __forceinline__ ull pack2(float x, float y) {
    ull r; asm("mov.b64 %0,{%1,%2};" : "=l"(r) : "f"(x), "f"(y)); return r;
}
__device__ __forceinline__ void unpack2(ull v, float& x, float& y) {
    asm("mov.b64 {%0,%1},%2;" : "=f"(x), "=f"(y) : "l"(v));
}
__device__ __forceinline__ ull fma2(ull a, ull b, ull c) {
    ull d; asm("fma.rn.f32x2 %0,%1,%2,%3;" : "=l"(d) : "l"(a), "l"(b), "l"(c)); return d;
}

// ---------------- scratch (static device globals) ---------------------------
__device__ float  g_h1[N_NODES * HID];
__device__ float  g_s1[N_NODES * HID];
__device__ float  g_agg[N_NODES * HID];
__device__ double g_sum16[HID];
__device__ double g_M[HID * HID];
__device__ float  g_scale[DIM];
__device__ float  g_shift[DIM];
__device__ int    g_row_ptr[N_NODES + 1];
__device__ unsigned int g_cnt = 0;

#define TB 256
#define NODE_BLK ((N_NODES + TB - 1) / TB)          // 391
#define RP_BLK   ((N_NODES + 1 + TB - 1) / TB)      // 391
#define SPMM_BLK ((N_NODES + 15) / 16)              // 6250 (16 threads/row)
#define STATS_G  296
#define STATS_TILE 128
#define N_TILES  ((N_NODES + STATS_TILE - 1) / STATS_TILE)   // 782

// ---------------- fused: row_ptr build + y[N,16] = x[N,128] @ W[128,16] ----
__global__ void prolog_kernel(const int* __restrict__ row, const float* __restrict__ x,
                              const float* __restrict__ W, float* __restrict__ y) {
    if (blockIdx.x >= NODE_BLK) {
        int i = (blockIdx.x - NODE_BLK) * TB + threadIdx.x;
        if (i > N_NODES) return;
        int lo = 0, hi = N_EDGES;
        while (lo < hi) {
            int mid = (lo + hi) >> 1;
            if (row[mid] < i) lo = mid + 1; else hi = mid;
        }
        g_row_ptr[i] = lo;
        return;
    }
    __shared__ __align__(16) float Ws[DIM * HID];
    for (int i = threadIdx.x; i < DIM * HID; i += TB) Ws[i] = W[i];
    __syncthreads();
    int n = blockIdx.x * TB + threadIdx.x;
    if (n >= N_NODES) return;
    ull acc2[8];
    #pragma unroll
    for (int j = 0; j < 8; j++) acc2[j] = 0ull;
    const float4* xr = reinterpret_cast<const float4*>(x + (size_t)n * DIM);
    #pragma unroll 4
    for (int d4 = 0; d4 < DIM / 4; d4++) {
        float4 xv = xr[d4];
        #pragma unroll
        for (int dd = 0; dd < 4; dd++) {
            float xd = (&xv.x)[dd];
            ull xb = pack2(xd, xd);
            const ulonglong2* wr = reinterpret_cast<const ulonglong2*>(&Ws[(d4 * 4 + dd) * HID]);
            #pragma unroll
            for (int p = 0; p < 4; p++) {
                ulonglong2 w = wr[p];
                acc2[p * 2 + 0] = fma2(xb, w.x, acc2[p * 2 + 0]);
                acc2[p * 2 + 1] = fma2(xb, w.y, acc2[p * 2 + 1]);
            }
        }
    }
    ull* yr = reinterpret_cast<ull*>(y + (size_t)n * HID);
    #pragma unroll
    for (int j = 0; j < 8; j++) yr[j] = acc2[j];
}

// ---------------- 16-wide SpMM: 16 threads/row (4 quads), float4 gathers ----
template<bool RELU>
__global__ void spmm16(const float4* __restrict__ h, const float* __restrict__ vals,
                       const int* __restrict__ col, const float4* __restrict__ bias4,
                       float4* __restrict__ out) {
    int t = threadIdx.x;
    int q = t & 3;
    int sub = (t >> 2) & 3;
    int r = blockIdx.x * 16 + (t >> 4);
    if (r >= N_NODES) return;
    int e0 = g_row_ptr[r], e1 = g_row_ptr[r + 1];
    float4 acc = make_float4(0.f, 0.f, 0.f, 0.f);
    int e = e0 + sub * 4;
    while (e + 4 <= e1) {
        int   c0 = col[e],     c1 = col[e + 1],  c2 = col[e + 2],  c3 = col[e + 3];
        float v0 = vals[e],    v1 = vals[e + 1], v2 = vals[e + 2], v3 = vals[e + 3];
        float4 h0 = h[(size_t)c0 * 4 + q];
        float4 h1 = h[(size_t)c1 * 4 + q];
        float4 h2 = h[(size_t)c2 * 4 + q];
        float4 h3 = h[(size_t)c3 * 4 + q];
        acc.x += v0 * h0.x; acc.y += v0 * h0.y; acc.z += v0 * h0.z; acc.w += v0 * h0.w;
        acc.x += v1 * h1.x; acc.y += v1 * h1.y; acc.z += v1 * h1.z; acc.w += v1 * h1.w;
        acc.x += v2 * h2.x; acc.y += v2 * h2.y; acc.z += v2 * h2.z; acc.w += v2 * h2.w;
        acc.x += v3 * h3.x; acc.y += v3 * h3.y; acc.z += v3 * h3.z; acc.w += v3 * h3.w;
        e += 16;
    }
    int eend = min(e + 4, e1);
    for (; e < eend; e++) {
        float v = vals[e];
        float4 hv = h[(size_t)col[e] * 4 + q];
        acc.x += v * hv.x; acc.y += v * hv.y; acc.z += v * hv.z; acc.w += v * hv.w;
    }
    #pragma unroll
    for (int m = 4; m <= 8; m <<= 1) {
        acc.x += __shfl_xor_sync(0xffffffffu, acc.x, m);
        acc.y += __shfl_xor_sync(0xffffffffu, acc.y, m);
        acc.z += __shfl_xor_sync(0xffffffffu, acc.z, m);
        acc.w += __shfl_xor_sync(0xffffffffu, acc.w, m);
    }
    if (sub == 0) {
        if (RELU) {
            float4 b = bias4[q];
            acc.x = fmaxf(acc.x + b.x, 0.f);
            acc.y = fmaxf(acc.y + b.y, 0.f);
            acc.z = fmaxf(acc.z + b.z, 0.f);
            acc.w = fmaxf(acc.w + b.w, 0.f);
        }
        out[(size_t)r * 4 + q] = acc;
    }
}

// ---------------- stats: thread-per-M-entry, 4-way split chains -------------
// thread t owns M[j][k], j=t>>4, k=t&15.  Last block computes BN affine.
__global__ void stats16_bn(const float* __restrict__ agg,
                           const float* __restrict__ W2,
                           const float* __restrict__ gamma,
                           const float* __restrict__ beta) {
    __shared__ __align__(16) float rows[STATS_TILE * HID];   // 8KB
    int t = threadIdx.x;
    if (blockIdx.x == 0 && t == 0) { /* nothing */ }
    int j = t >> 4, k = t & 15;
    float m0 = 0.f, m1 = 0.f, m2 = 0.f, m3 = 0.f;
    float s0 = 0.f, s1 = 0.f, s2 = 0.f, s3 = 0.f;
    for (int tile = blockIdx.x; tile < N_TILES; tile += STATS_G) {
        int r0 = tile * STATS_TILE;
        int nr = min(STATS_TILE, N_NODES - r0);      // 128, last tile 32
        __syncthreads();
        for (int i = t; i < nr * 4; i += TB)
            reinterpret_cast<float4*>(rows)[i] =
                reinterpret_cast<const float4*>(agg + (size_t)r0 * HID)[i];
        __syncthreads();
        #pragma unroll 2
        for (int rr = 0; rr + 4 <= nr; rr += 4) {
            float aj0 = rows[(rr + 0) * HID + j], ak0 = rows[(rr + 0) * HID + k];
            float aj1 = rows[(rr + 1) * HID + j], ak1 = rows[(rr + 1) * HID + k];
            float aj2 = rows[(rr + 2) * HID + j], ak2 = rows[(rr + 2) * HID + k];
            float aj3 = rows[(rr + 3) * HID + j], ak3 = rows[(rr + 3) * HID + k];
            m0 += aj0 * ak0; m1 += aj1 * ak1; m2 += aj2 * ak2; m3 += aj3 * ak3;
            if (j == 0) { s0 += ak0; s1 += ak1; s2 += ak2; s3 += ak3; }
        }
    }
    atomicAdd(&g_M[t], (double)((m0 + m1) + (m2 + m3)));
    if (j == 0) atomicAdd(&g_sum16[k], (double)((s0 + s1) + (s2 + s3)));

    // ---- last block computes BN affine ----
    __threadfence();
    __shared__ unsigned int sIsLast;
    if (t == 0) {
        unsigned int old = atomicAdd(&g_cnt, 1u);
        sIsLast = (old == gridDim.x - 1) ? 1u : 0u;
    }
    __syncthreads();
    if (!sIsLast) return;
    __shared__ double Ms[HID * HID];
    __shared__ double Ss[HID];
    Ms[t] = g_M[t];
    if (t < HID) Ss[t] = g_sum16[t];
    __syncthreads();
    if (t < DIM) {
        float wf[HID];
        #pragma unroll
        for (int kk = 0; kk < HID; kk++) wf[kk] = W2[kk * DIM + t];
        // sum . w  (4-way split double chain)
        double sp0 = 0.0, sp1 = 0.0, sp2 = 0.0, sp3 = 0.0;
        #pragma unroll
        for (int kk = 0; kk < HID; kk += 4) {
            sp0 += Ss[kk + 0] * (double)wf[kk + 0];
            sp1 += Ss[kk + 1] * (double)wf[kk + 1];
            sp2 += Ss[kk + 2] * (double)wf[kk + 2];
            sp3 += Ss[kk + 3] * (double)wf[kk + 3];
        }
        double sm = (sp0 + sp1) + (sp2 + sp3);
        // w^T M w with fp32 products, 8-way split double chains
        double q8[8];
        #pragma unroll
        for (int p = 0; p < 8; p++) q8[p] = 0.0;
        #pragma unroll
        for (int a = 0; a < HID; a++) {
            float wa = wf[a];
            #pragma unroll
            for (int b = 0; b < HID; b++)
                q8[b & 7] += Ms[a * HID + b] * (double)(wa * wf[b]);
        }
        double qv = ((q8[0] + q8[1]) + (q8[2] + q8[3])) + ((q8[4] + q8[5]) + (q8[6] + q8[7]));
        const double invN = 1.0 / (double)N_NODES;
        double sn = sm * invN;
        float var = (float)(qv * invN - sn * sn);
        float scale = rsqrtf(var + BN_EPS) * gamma[t];
        g_scale[t] = scale;
        g_shift[t] = beta[t] - (float)sn * scale;   // b2 cancels in (h2-mean)
    }
    __syncthreads();
    // reset accumulators for next layer (ordered: only last block runs this)
    g_M[t] = 0.0;
    if (t < HID) g_sum16[t] = 0.0;
    if (t == 0) g_cnt = 0;
}

// ---------------- zero stats before first use -------------------------------
__global__ void zero_stats() {
    int t = threadIdx.x;
    if (t < HID * HID) g_M[t] = 0.0;
    if (t < HID) g_sum16[t] = 0.0;
    if (t == 0) g_cnt = 0;
}

// ---------------- fused: h1 = relu(bn(agg@W2)) @ W1next  (f32x2 packed) -----
__global__ void fused_bn_gemm(const float* __restrict__ agg, const float* __restrict__ W2,
                              const float* __restrict__ W1n, float* __restrict__ y) {
    __shared__ __align__(16) float W2s[HID * DIM];
    __shared__ __align__(16) float W1s[DIM * HID];
    __shared__ __align__(16) float scl[DIM];
    __shared__ __align__(16) float sft[DIM];
    for (int i = threadIdx.x; i < HID * DIM; i += TB) {
        W2s[i] = W2[i];
        W1s[i] = W1n[i];
    }
    for (int i = threadIdx.x; i < DIM; i += TB) {
        scl[i] = g_scale[i];
        sft[i] = g_shift[i];
    }
    __syncthreads();
    int n = blockIdx.x * TB + threadIdx.x;
    if (n >= N_NODES) return;
    ull a2[HID];
    {
        const float4* ar = reinterpret_cast<const float4*>(agg + (size_t)n * HID);
        #pragma unroll
        for (int k4 = 0; k4 < 4; k4++) {
            float4 v = ar[k4];
            a2[k4*4+0] = pack2(v.x, v.x);
            a2[k4*4+1] = pack2(v.y, v.y);
            a2[k4*4+2] = pack2(v.z, v.z);
            a2[k4*4+3] = pack2(v.w, v.w);
        }
    }
    ull acc2[8];
    #pragma unroll
    for (int j = 0; j < 8; j++) acc2[j] = 0ull;
    #pragma unroll 2
    for (int cb = 0; cb < DIM; cb += 4) {
        ull t01 = 0ull, t23 = 0ull;
        const ulonglong2* w2p = reinterpret_cast<const ulonglong2*>(&W2s[cb]);
        #pragma unroll
        for (int k = 0; k < HID; k++) {
            ulonglong2 w = w2p[k * (DIM / 4)];
            t01 = fma2(a2[k], w.x, t01);
            t23 = fma2(a2[k], w.y, t23);
        }
        ulonglong2 sc = *reinterpret_cast<const ulonglong2*>(&scl[cb]);
        ulonglong2 sf = *reinterpret_cast<const ulonglong2*>(&sft[cb]);
        t01 = fma2(t01, sc.x, sf.x);
        t23 = fma2(t23, sc.y, sf.y);
        float v0, v1, v2, v3;
        unpack2(t01, v0, v1);
        unpack2(t23, v2, v3);
        v0 = fmaxf(v0, 0.f); v1 = fmaxf(v1, 0.f);
        v2 = fmaxf(v2, 0.f); v3 = fmaxf(v3, 0.f);
        ull vb[4] = { pack2(v0, v0), pack2(v1, v1), pack2(v2, v2), pack2(v3, v3) };
        #pragma unroll
        for (int c = 0; c < 4; c++) {
            const ulonglong2* w1p = reinterpret_cast<const ulonglong2*>(&W1s[(cb + c) * HID]);
            #pragma unroll
            for (int p = 0; p < 4; p++) {
                ulonglong2 w = w1p[p];
                acc2[p * 2 + 0] = fma2(vb[c], w.x, acc2[p * 2 + 0]);
                acc2[p * 2 + 1] = fma2(vb[c], w.y, acc2[p * 2 + 1]);
            }
        }
    }
    ull* yr = reinterpret_cast<ull*>(y + (size_t)n * HID);
    #pragma unroll
    for (int j = 0; j < 8; j++) yr[j] = acc2[j];
}

// ---------------- out[N,40] = agg[N,16] @ W[16,40] + b  (f32x2 packed) ------
__global__ void out_gemm(const float* __restrict__ agg, const float* __restrict__ W,
                         const float* __restrict__ b, float* __restrict__ out) {
    __shared__ __align__(16) float Ws[HID * NCLS];
    __shared__ __align__(16) float bs[NCLS];
    for (int i = threadIdx.x; i < HID * NCLS; i += TB) Ws[i] = W[i];
    if (threadIdx.x < NCLS) bs[threadIdx.x] = b[threadIdx.x];
    __syncthreads();
    int n = blockIdx.x * TB + threadIdx.x;
    if (n >= N_NODES) return;
    ull a2[HID];
    {
        const float4* ar = reinterpret_cast<const float4*>(agg + (size_t)n * HID);
        #pragma unroll
        for (int k4 = 0; k4 < 4; k4++) {
            float4 v = ar[k4];
            a2[k4*4+0] = pack2(v.x, v.x);
            a2[k4*4+1] = pack2(v.y, v.y);
            a2[k4*4+2] = pack2(v.z, v.z);
            a2[k4*4+3] = pack2(v.w, v.w);
        }
    }
    ull o2[NCLS / 2];
    const ull* bp = reinterpret_cast<const ull*>(bs);
    #pragma unroll
    for (int p = 0; p < NCLS / 2; p++) o2[p] = bp[p];
    #pragma unroll
    for (int k = 0; k < HID; k++) {
        const ull* wr = reinterpret_cast<const ull*>(&Ws[k * NCLS]);
        #pragma unroll
        for (int p = 0; p < NCLS / 2; p++)
            o2[p] = fma2(a2[k], wr[p], o2[p]);
    }
    ull* orow = reinterpret_cast<ull*>(out + (size_t)n * NCLS);
    #pragma unroll
    for (int p = 0; p < NCLS / 2; p++) orow[p] = o2[p];
}

// ============================================================================
extern "C" void kernel_launch(void* const* d_in, const int* in_sizes, int n_in,
                              void* d_out, int out_size) {
    const float* x     = (const float*)d_in[0];
    const float* vals  = (const float*)d_in[1];
    const float* W1    = (const float*)d_in[2];   // (3,128,16)
    const float* b1    = (const float*)d_in[3];   // (3,16)
    const float* W2    = (const float*)d_in[4];   // (3,16,128)
    const float* b2    = (const float*)d_in[5];   // (3,128)  (cancels in BN)
    const float* gamma = (const float*)d_in[6];   // (3,128)
    const float* beta  = (const float*)d_in[7];   // (3,128)
    const float* W1f   = (const float*)d_in[8];   // (128,16)
    const float* b1f   = (const float*)d_in[9];   // (16,)
    const float* W2f   = (const float*)d_in[10];  // (16,40)
    const float* b2f   = (const float*)d_in[11];  // (40,)
    const int*   row   = (const int*)d_in[12];
    const int*   col   = (const int*)d_in[13];
    float* out = (float*)d_out;
    (void)b2;

    float *p_h1, *p_s1, *p_agg;
    cudaGetSymbolAddress((void**)&p_h1,  g_h1);
    cudaGetSymbolAddress((void**)&p_s1,  g_s1);
    cudaGetSymbolAddress((void**)&p_agg, g_agg);

    zero_stats<<<1, 256>>>();
    prolog_kernel<<<NODE_BLK + RP_BLK, TB>>>(row, x, W1, p_h1);

    for (int i = 0; i < 3; i++) {
        spmm16<true><<<SPMM_BLK, TB>>>((const float4*)p_h1, vals, col,
                                       (const float4*)(b1 + i * HID), (float4*)p_s1);
        spmm16<false><<<SPMM_BLK, TB>>>((const float4*)p_s1, vals, col,
                                        nullptr, (float4*)p_agg);
        stats16_bn<<<STATS_G, TB>>>(p_agg, W2 + (size_t)i * HID * DIM,
                                    gamma + i * DIM, beta + i * DIM);
        const float* Wnext = (i < 2) ? (W1 + (size_t)(i + 1) * DIM * HID) : W1f;
        fused_bn_gemm<<<NODE_BLK, TB>>>(p_agg, W2 + (size_t)i * HID * DIM, Wnext, p_h1);
    }

    spmm16<true><<<SPMM_BLK, TB>>>((const float4*)p_h1, vals, col,
                                   (const float4*)b1f, (float4*)p_s1);
    spmm16<false><<<SPMM_BLK, TB>>>((const float4*)p_s1, vals, col,
                                    nullptr, (float4*)p_agg);
    out_gemm<<<NODE_BLK, TB>>>(p_agg, W2f, b2f, out);
}